// round 4
// baseline (speedup 1.0000x reference)
#include <cuda_runtime.h>
#include <cstdint>

// ---------------------------------------------------------------------------
// EfficientAttention_Mapping: B=256, 2N=4096 (two halves of N=2048), D=3, DK=64
//
// Exact reformulation accumulated per (b,half):
//   qbar[j] = sum_n exp(lq[n,j]) / sum_j' exp(lq[n,j'])
//   kden[j] = sum_n exp(lk[n,j])
//   M[j][e] = sum_n exp(lk[n,j]) * x[n,e]     (e = 0..2)
// then
//   knum[j][d] = sum_e M[j][e]*Wv[e,d] + bv[d]*kden[j]
//   out_half[d] = (1/N) * sum_j qbar[j] * knum[j][d] / kden[j]
// Finalize (combine 8 partial blocks per batch, Wv fold, half-average,
// L2-normalize) is fused via a last-CTA-per-batch atomic-counter pattern.
// ---------------------------------------------------------------------------

typedef unsigned long long ull;

__device__ __forceinline__ ull pack2(float lo, float hi) {
    ull r; asm("mov.b64 %0, {%1, %2};" : "=l"(r) : "f"(lo), "f"(hi)); return r;
}
__device__ __forceinline__ void unpack2(ull v, float& lo, float& hi) {
    asm("mov.b64 {%0, %1}, %2;" : "=f"(lo), "=f"(hi) : "l"(v));
}
__device__ __forceinline__ ull fma2(ull a, ull b, ull c) {
    ull d; asm("fma.rn.f32x2 %0, %1, %2, %3;" : "=l"(d) : "l"(a), "l"(b), "l"(c)); return d;
}
__device__ __forceinline__ ull add2(ull a, ull b) {
    ull d; asm("add.rn.f32x2 %0, %1, %2;" : "=l"(d) : "l"(a), "l"(b)); return d;
}
__device__ __forceinline__ float ex2f(float x) {
    float y; asm("ex2.approx.ftz.f32 %0, %1;" : "=f"(y) : "f"(x)); return y;
}
__device__ __forceinline__ float rcpf(float x) {
    float y; asm("rcp.approx.ftz.f32 %0, %1;" : "=f"(y) : "f"(x)); return y;
}

#define LOG2E_F 1.4426950408889634f
#define MAGIC_F 12582912.0f   // 1.5 * 2^23

// FMA-pipe exp2 of a packed pair (inputs already in log2 domain).
// Range reduce with the magic-number trick, degree-5 Taylor for 2^f on
// [-0.5, 0.5] (rel err ~2.4e-6), splice integer part into the exponent field.
__device__ __forceinline__ ull exp2_poly2(ull t2) {
    const ull MAG2  = pack2(MAGIC_F, MAGIC_F);
    const ull NMAG2 = pack2(-MAGIC_F, -MAGIC_F);
    const ull NONE2 = pack2(-1.0f, -1.0f);
    const ull C5 = pack2(1.3333558e-3f, 1.3333558e-3f);
    const ull C4 = pack2(9.6181291e-3f, 9.6181291e-3f);
    const ull C3 = pack2(5.5504109e-2f, 5.5504109e-2f);
    const ull C2 = pack2(2.4022651e-1f, 2.4022651e-1f);
    const ull C1 = pack2(6.9314718e-1f, 6.9314718e-1f);
    const ull C0 = pack2(1.0f, 1.0f);

    ull r2 = add2(t2, MAG2);          // magic + rint(t)
    ull d2 = add2(r2, NMAG2);         // rint(t) exactly
    ull f2 = fma2(d2, NONE2, t2);     // f = t - rint(t), in [-0.5, 0.5]

    ull p = fma2(C5, f2, C4);
    p = fma2(p, f2, C3);
    p = fma2(p, f2, C2);
    p = fma2(p, f2, C1);
    p = fma2(p, f2, C0);

    float rl, rh, pl, ph;
    unpack2(r2, rl, rh);
    unpack2(p, pl, ph);
    // bits(magic + n) = 0x4B400000 + n; low 9 bits of 0x4B400000 are zero,
    // so (bits << 23) == (n << 23) mod 2^32 — add straight into the exponent.
    int sl = __float_as_int(rl) << 23;
    int sh = __float_as_int(rh) << 23;
    float el = __int_as_float(__float_as_int(pl) + sl);
    float eh = __int_as_float(__float_as_int(ph) + sh);
    return pack2(el, eh);
}

// Scratch: 2048 row-blocks x 320 partials (qbar[64], M0[64], M1[64], M2[64], kden[64])
__device__ float g_part[2048 * 320];
__device__ int   g_cnt[256];   // zero-init; reset by finalizer each replay

// ---------------------------------------------------------------------------
// Fused kernel: each CTA handles 512 consecutive rows of the flattened
// [256*4096, 3] input. 256 threads = 32 groups of 8; group handles 16 rows;
// thread c in a group owns 8 j's: {c+16u, c+16u+8 : u=0..3} as f32x2 pairs.
// Last CTA of each batch (8 CTAs/batch) performs the finalize.
// ---------------------------------------------------------------------------
__global__ __launch_bounds__(256)
void ea_fused_kernel(const float* __restrict__ xin,
                     const float* __restrict__ Wq, const float* __restrict__ bq,
                     const float* __restrict__ Wk, const float* __restrict__ bk,
                     const float* __restrict__ Wv, const float* __restrict__ bv,
                     float* __restrict__ out)
{
    __shared__ ull         xs2[512 * 3];       // 12 KB: x chunk, each value duplicated in a pair
    __shared__ ulonglong2  wsu[4][4][8];       // 2 KB: weight pairs, pre-scaled by log2e
    __shared__ float       red[5][8][64];      // 10 KB: end-of-CTA reduction
    __shared__ int         s_old;
    __shared__ float       fsh[2][3];
    __shared__ float       ohalf[2][3];

    const int tid = threadIdx.x;
    const int blk = blockIdx.x;                // 0..2047; batch = blk>>3

    // --- stage x chunk as duplicated pairs (1536 scalars, coalesced) ---
    {
        const float* src = xin + (size_t)blk * 1536;
        #pragma unroll
        for (int i = tid; i < 1536; i += 256) {
            const float v = src[i];
            xs2[i] = pack2(v, v);
        }
    }

    // --- stage weights: wsu[sp][u][c] holds two f32x2 pairs for j0=c+16u, j1=j0+8
    {
        float4* wf = reinterpret_cast<float4*>(&wsu[0][0][0]);
        for (int i = tid; i < 128; i += 256) {
            int c  = i & 7;
            int u  = (i >> 3) & 3;
            int sp = i >> 5;
            int j0 = c + 16 * u, j1 = j0 + 8;
            float a, b, cc, d;
            if (sp == 0)      { a = Wq[j0];       b = Wq[j1];       cc = Wq[64 + j0];  d = Wq[64 + j1]; }
            else if (sp == 1) { a = Wq[128 + j0]; b = Wq[128 + j1]; cc = bq[j0];       d = bq[j1]; }
            else if (sp == 2) { a = Wk[j0];       b = Wk[j1];       cc = Wk[64 + j0];  d = Wk[64 + j1]; }
            else              { a = Wk[128 + j0]; b = Wk[128 + j1]; cc = bk[j0];       d = bk[j1]; }
            wf[i] = make_float4(a * LOG2E_F, b * LOG2E_F, cc * LOG2E_F, d * LOG2E_F);
        }
    }
    __syncthreads();

    const int c = tid & 7;        // j-slice index within group
    const int g = tid >> 3;       // group = row lane (32 groups)

    const ull Z = pack2(0.0f, 0.0f);
    ull qb2[4], M0[4], M1[4], M2a[4], kd2[4];
    #pragma unroll
    for (int u = 0; u < 4; ++u) { qb2[u] = Z; M0[u] = Z; M1[u] = Z; M2a[u] = Z; kd2[u] = Z; }

    #pragma unroll 1
    for (int it = 0; it < 16; ++it) {
        const int row = g + (it << 5);
        const ull X0 = xs2[row * 3 + 0];
        const ull X1 = xs2[row * 3 + 1];
        const ull X2 = xs2[row * 3 + 2];

        ull sq2 = Z;
        ull eqs[4];

        #pragma unroll
        for (int u = 0; u < 4; ++u) {
            const ulonglong2 wq01 = wsu[0][u][c];   // (wq0 pair, wq1 pair)
            const ulonglong2 wq2b = wsu[1][u][c];   // (wq2 pair, bq  pair)
            const ulonglong2 wk01 = wsu[2][u][c];
            const ulonglong2 wk2b = wsu[3][u][c];

            ull lq = fma2(X0, wq01.x, fma2(X1, wq01.y, fma2(X2, wq2b.x, wq2b.y)));
            ull lk = fma2(X0, wk01.x, fma2(X1, wk01.y, fma2(X2, wk2b.x, wk2b.y)));

            ull eq;
            if (u == 0) {
                // FMA-pipe polynomial for this q-pair: offloads 2 of 16 exps/row
                // from the oversubscribed MUFU pipe.
                eq = exp2_poly2(lq);
            } else {
                float a, b;
                unpack2(lq, a, b);
                eq = pack2(ex2f(a), ex2f(b));
            }
            float a, b;
            unpack2(lk, a, b);
            const ull ek = pack2(ex2f(a), ex2f(b));

            sq2    = add2(sq2, eq);
            eqs[u] = eq;
            kd2[u] = add2(kd2[u], ek);
            M0[u]  = fma2(ek, X0, M0[u]);
            M1[u]  = fma2(ek, X1, M1[u]);
            M2a[u] = fma2(ek, X2, M2a[u]);
        }

        // row softmax denominator: local pair sum + reduce across 8 threads of group
        float slo, shi;
        unpack2(sq2, slo, shi);
        float sq = slo + shi;
        sq += __shfl_xor_sync(0xffffffffu, sq, 1);
        sq += __shfl_xor_sync(0xffffffffu, sq, 2);
        sq += __shfl_xor_sync(0xffffffffu, sq, 4);
        const float r = rcpf(sq);
        const ull  R = pack2(r, r);

        #pragma unroll
        for (int u = 0; u < 4; ++u) qb2[u] = fma2(eqs[u], R, qb2[u]);
    }

    // --- reduce the 4 groups within each warp (lanes differ by bits 3,4) ---
    #pragma unroll
    for (int u = 0; u < 4; ++u) {
        qb2[u] = add2(qb2[u], __shfl_xor_sync(0xffffffffu, qb2[u], 8));
        qb2[u] = add2(qb2[u], __shfl_xor_sync(0xffffffffu, qb2[u], 16));
        M0[u]  = add2(M0[u],  __shfl_xor_sync(0xffffffffu, M0[u],  8));
        M0[u]  = add2(M0[u],  __shfl_xor_sync(0xffffffffu, M0[u],  16));
        M1[u]  = add2(M1[u],  __shfl_xor_sync(0xffffffffu, M1[u],  8));
        M1[u]  = add2(M1[u],  __shfl_xor_sync(0xffffffffu, M1[u],  16));
        M2a[u] = add2(M2a[u], __shfl_xor_sync(0xffffffffu, M2a[u], 8));
        M2a[u] = add2(M2a[u], __shfl_xor_sync(0xffffffffu, M2a[u], 16));
        kd2[u] = add2(kd2[u], __shfl_xor_sync(0xffffffffu, kd2[u], 8));
        kd2[u] = add2(kd2[u], __shfl_xor_sync(0xffffffffu, kd2[u], 16));
    }

    const int lane = tid & 31;
    const int w    = tid >> 5;
    if (lane < 8) {
        #pragma unroll
        for (int u = 0; u < 4; ++u) {
            const int j0 = lane + 16 * u, j1 = j0 + 8;
            float a, b;
            unpack2(qb2[u], a, b); red[0][w][j0] = a; red[0][w][j1] = b;
            unpack2(M0[u],  a, b); red[1][w][j0] = a; red[1][w][j1] = b;
            unpack2(M1[u],  a, b); red[2][w][j0] = a; red[2][w][j1] = b;
            unpack2(M2a[u], a, b); red[3][w][j0] = a; red[3][w][j1] = b;
            unpack2(kd2[u], a, b); red[4][w][j0] = a; red[4][w][j1] = b;
        }
    }
    __syncthreads();

    for (int vi = tid; vi < 320; vi += 256) {
        const int acc = vi >> 6, j = vi & 63;
        float s = 0.0f;
        #pragma unroll
        for (int ww = 0; ww < 8; ++ww) s += red[acc][ww][j];
        g_part[(size_t)blk * 320 + vi] = s;
    }

    // ---------------- fused finalize: last CTA per batch ----------------
    const int bb = blk >> 3;
    __syncthreads();                    // all g_part stores of this CTA done
    if (tid == 0) {
        __threadfence();                // publish g_part before counter bump
        s_old = atomicAdd(&g_cnt[bb], 1);
    }
    __syncthreads();
    if (s_old != 7) return;

    __threadfence();                    // acquire: see all 8 blocks' g_part

    const int j = tid;                  // only tid<64 participates in j-work
    if (j < 64) {
        for (int h = 0; h < 2; ++h) {
            float qb = 0.0f, m0 = 0.0f, m1 = 0.0f, m2 = 0.0f, kd = 0.0f;
            const size_t base = (size_t)(bb * 8 + h * 4) * 320;
            #pragma unroll
            for (int s = 0; s < 4; ++s) {
                const float* p = g_part + base + (size_t)s * 320;
                qb += p[j];
                m0 += p[64 + j];
                m1 += p[128 + j];
                m2 += p[192 + j];
                kd += p[256 + j];
            }
            const float rkd = 1.0f / kd;
            float t[3];
            #pragma unroll
            for (int d = 0; d < 3; ++d) {
                const float kn = m0 * Wv[0 * 3 + d] + m1 * Wv[1 * 3 + d]
                               + m2 * Wv[2 * 3 + d] + bv[d] * kd;
                t[d] = qb * (kn * rkd);
            }
            #pragma unroll
            for (int o = 16; o >= 1; o >>= 1) {
                t[0] += __shfl_xor_sync(0xffffffffu, t[0], o);
                t[1] += __shfl_xor_sync(0xffffffffu, t[1], o);
                t[2] += __shfl_xor_sync(0xffffffffu, t[2], o);
            }
            const int ww = j >> 5;
            if ((j & 31) == 0) { fsh[ww][0] = t[0]; fsh[ww][1] = t[1]; fsh[ww][2] = t[2]; }
            __syncwarp(0xffffffffu);
            // cross-warp combine done below after a CTA-wide sync
            if (h == 0) {
                __syncthreads();
                if (j == 0)
                    for (int d = 0; d < 3; ++d)
                        ohalf[0][d] = (fsh[0][d] + fsh[1][d]) * (1.0f / 2048.0f);
                __syncthreads();
            }
        }
    } else {
        // non-participating threads still hit the CTA-wide syncs above
        __syncthreads();
        __syncthreads();
    }
    __syncthreads();
    if (j == 0) {
        const float oh1_0 = (fsh[0][0] + fsh[1][0]) * (1.0f / 2048.0f);
        const float oh1_1 = (fsh[0][1] + fsh[1][1]) * (1.0f / 2048.0f);
        const float oh1_2 = (fsh[0][2] + fsh[1][2]) * (1.0f / 2048.0f);
        const float a0 = 0.5f * (ohalf[0][0] + oh1_0);
        const float a1 = 0.5f * (ohalf[0][1] + oh1_1);
        const float a2 = 0.5f * (ohalf[0][2] + oh1_2);
        const float inv = rsqrtf(a0 * a0 + a1 * a1 + a2 * a2);
        out[bb * 3 + 0] = a0 * inv;
        out[bb * 3 + 1] = a1 * inv;
        out[bb * 3 + 2] = a2 * inv;
        g_cnt[bb] = 0;                  // reset for next graph replay
    }
}

// ---------------------------------------------------------------------------
extern "C" void kernel_launch(void* const* d_in, const int* in_sizes, int n_in,
                              void* d_out, int out_size)
{
    const float* xin = (const float*)d_in[0];
    const float* Wq  = (const float*)d_in[1];
    const float* bq  = (const float*)d_in[2];
    const float* Wk  = (const float*)d_in[3];
    const float* bk  = (const float*)d_in[4];
    const float* Wv  = (const float*)d_in[5];
    const float* bv  = (const float*)d_in[6];
    float* out = (float*)d_out;

    ea_fused_kernel<<<2048, 256>>>(xin, Wq, bq, Wk, bk, Wv, bv, out);
}

// round 6
// speedup vs baseline: 1.1894x; 1.1894x over previous
#include <cuda_runtime.h>
#include <cstdint>

// ---------------------------------------------------------------------------
// EfficientAttention_Mapping: B=256, 2N=4096 (two halves of N=2048), D=3, DK=64
//
// Exact reformulation accumulated per (b,half):
//   qbar[j] = sum_n exp(lq[n,j]) / sum_j' exp(lq[n,j'])
//   kden[j] = sum_n exp(lk[n,j])
//   M[j][e] = sum_n exp(lk[n,j]) * x[n,e]     (e = 0..2)
// then
//   knum[j][d] = sum_e M[j][e]*Wv[e,d] + bv[d]*kden[j]
//   out_half[d] = (1/N) * sum_j qbar[j] * knum[j][d] / kden[j]
//
// Layout (round 4): 256 thr/CTA = 16 groups x 16 threads. Each group handles
// 32 rows; thread c owns 4 j's: pairs (c+32u, c+32u+16), u=0..1. This halves
// register pressure vs the 8-j layout (weights 32 regs, accums 20 regs) so
// 3 CTAs/SM fit -> 24 warps/SM to hide MUFU/shfl/LDS latency.
// ---------------------------------------------------------------------------

typedef unsigned long long ull;

__device__ __forceinline__ ull pack2(float lo, float hi) {
    ull r; asm("mov.b64 %0, {%1, %2};" : "=l"(r) : "f"(lo), "f"(hi)); return r;
}
__device__ __forceinline__ void unpack2(ull v, float& lo, float& hi) {
    asm("mov.b64 {%0, %1}, %2;" : "=f"(lo), "=f"(hi) : "l"(v));
}
__device__ __forceinline__ ull fma2(ull a, ull b, ull c) {
    ull d; asm("fma.rn.f32x2 %0, %1, %2, %3;" : "=l"(d) : "l"(a), "l"(b), "l"(c)); return d;
}
__device__ __forceinline__ ull add2(ull a, ull b) {
    ull d; asm("add.rn.f32x2 %0, %1, %2;" : "=l"(d) : "l"(a), "l"(b)); return d;
}
__device__ __forceinline__ float ex2f(float x) {
    float y; asm("ex2.approx.ftz.f32 %0, %1;" : "=f"(y) : "f"(x)); return y;
}
__device__ __forceinline__ float rcpf(float x) {
    float y; asm("rcp.approx.ftz.f32 %0, %1;" : "=f"(y) : "f"(x)); return y;
}

#define LOG2E_F 1.4426950408889634f

// Scratch: 2048 row-blocks x 320 partials (qbar[64], M0[64], M1[64], M2[64], kden[64])
__device__ float g_part[2048 * 320];
__device__ int   g_cnt[256];   // zero-init; reset by finalizer each replay

__global__ __launch_bounds__(256, 3)
void ea_fused_kernel(const float* __restrict__ xin,
                     const float* __restrict__ Wq, const float* __restrict__ bq,
                     const float* __restrict__ Wk, const float* __restrict__ bk,
                     const float* __restrict__ Wv, const float* __restrict__ bv,
                     float* __restrict__ out)
{
    __shared__ ull         xs2[512 * 3];       // 12 KB: x chunk, value duplicated per pair
    __shared__ ulonglong2  wsu[4][2][16];      // 2 KB: weight pairs, pre-scaled by log2e
    __shared__ float       red[5][8][64];      // 10 KB: end-of-CTA reduction
    __shared__ int         s_old;
    __shared__ float       fsh[2][3];
    __shared__ float       ohalf[2][3];

    const int tid = threadIdx.x;
    const int blk = blockIdx.x;                // 0..2047; batch = blk>>3

    // --- stage x chunk as duplicated pairs (1536 scalars, coalesced) ---
    {
        const float* src = xin + (size_t)blk * 1536;
        #pragma unroll
        for (int i = tid; i < 1536; i += 256) {
            const float v = src[i];
            xs2[i] = pack2(v, v);
        }
    }

    // --- stage weights: wsu[sp][u][c]: pair (j0=c+32u, j1=j0+16)
    // sp0: (Wq row0 pair, Wq row1 pair)   sp1: (Wq row2 pair, bq pair)
    // sp2: (Wk row0 pair, Wk row1 pair)   sp3: (Wk row2 pair, bk pair)
    {
        float4* wf = reinterpret_cast<float4*>(&wsu[0][0][0]);
        for (int i = tid; i < 128; i += 256) {
            int c  = i & 15;
            int u  = (i >> 4) & 1;
            int sp = i >> 5;
            int j0 = c + 32 * u, j1 = j0 + 16;
            float a, b, cc, d;
            if (sp == 0)      { a = Wq[j0];       b = Wq[j1];       cc = Wq[64 + j0];  d = Wq[64 + j1]; }
            else if (sp == 1) { a = Wq[128 + j0]; b = Wq[128 + j1]; cc = bq[j0];       d = bq[j1]; }
            else if (sp == 2) { a = Wk[j0];       b = Wk[j1];       cc = Wk[64 + j0];  d = Wk[64 + j1]; }
            else              { a = Wk[128 + j0]; b = Wk[128 + j1]; cc = bk[j0];       d = bk[j1]; }
            wf[i] = make_float4(a * LOG2E_F, b * LOG2E_F, cc * LOG2E_F, d * LOG2E_F);
        }
    }
    __syncthreads();

    const int c = tid & 15;       // j-slice index within group (0..15)
    const int g = tid >> 4;       // group = row lane (16 groups)

    // hoist loop-invariant weights: 8 ulonglong2 = 32 regs
    const ulonglong2 wq01_0 = wsu[0][0][c], wq2b_0 = wsu[1][0][c];
    const ulonglong2 wk01_0 = wsu[2][0][c], wk2b_0 = wsu[3][0][c];
    const ulonglong2 wq01_1 = wsu[0][1][c], wq2b_1 = wsu[1][1][c];
    const ulonglong2 wk01_1 = wsu[2][1][c], wk2b_1 = wsu[3][1][c];

    const ull Z = pack2(0.0f, 0.0f);
    ull qb2[2], M0[2], M1[2], M2a[2], kd2[2];
    #pragma unroll
    for (int u = 0; u < 2; ++u) { qb2[u] = Z; M0[u] = Z; M1[u] = Z; M2a[u] = Z; kd2[u] = Z; }

    #pragma unroll 1
    for (int it = 0; it < 32; ++it) {
        const int row = g + (it << 4);
        const ull X0 = xs2[row * 3 + 0];
        const ull X1 = xs2[row * 3 + 1];
        const ull X2 = xs2[row * 3 + 2];

        // u = 0
        ull lq0 = fma2(X0, wq01_0.x, fma2(X1, wq01_0.y, fma2(X2, wq2b_0.x, wq2b_0.y)));
        ull lk0 = fma2(X0, wk01_0.x, fma2(X1, wk01_0.y, fma2(X2, wk2b_0.x, wk2b_0.y)));
        // u = 1
        ull lq1 = fma2(X0, wq01_1.x, fma2(X1, wq01_1.y, fma2(X2, wq2b_1.x, wq2b_1.y)));
        ull lk1 = fma2(X0, wk01_1.x, fma2(X1, wk01_1.y, fma2(X2, wk2b_1.x, wk2b_1.y)));

        float a, b;
        unpack2(lq0, a, b); const ull eq0 = pack2(ex2f(a), ex2f(b));
        unpack2(lq1, a, b); const ull eq1 = pack2(ex2f(a), ex2f(b));
        unpack2(lk0, a, b); const ull ek0 = pack2(ex2f(a), ex2f(b));
        unpack2(lk1, a, b); const ull ek1 = pack2(ex2f(a), ex2f(b));

        kd2[0] = add2(kd2[0], ek0);
        kd2[1] = add2(kd2[1], ek1);
        M0[0]  = fma2(ek0, X0, M0[0]);  M0[1]  = fma2(ek1, X0, M0[1]);
        M1[0]  = fma2(ek0, X1, M1[0]);  M1[1]  = fma2(ek1, X1, M1[1]);
        M2a[0] = fma2(ek0, X2, M2a[0]); M2a[1] = fma2(ek1, X2, M2a[1]);

        // row softmax denominator over 16 group threads (4 shfl steps)
        ull sq2 = add2(eq0, eq1);
        float slo, shi;
        unpack2(sq2, slo, shi);
        float sq = slo + shi;
        sq += __shfl_xor_sync(0xffffffffu, sq, 1);
        sq += __shfl_xor_sync(0xffffffffu, sq, 2);
        sq += __shfl_xor_sync(0xffffffffu, sq, 4);
        sq += __shfl_xor_sync(0xffffffffu, sq, 8);
        const float r = rcpf(sq);
        const ull  R = pack2(r, r);

        qb2[0] = fma2(eq0, R, qb2[0]);
        qb2[1] = fma2(eq1, R, qb2[1]);
    }

    // --- combine the 2 groups within each warp (lanes differ in bit 4) ---
    #pragma unroll
    for (int u = 0; u < 2; ++u) {
        qb2[u] = add2(qb2[u], __shfl_xor_sync(0xffffffffu, qb2[u], 16));
        M0[u]  = add2(M0[u],  __shfl_xor_sync(0xffffffffu, M0[u],  16));
        M1[u]  = add2(M1[u],  __shfl_xor_sync(0xffffffffu, M1[u],  16));
        M2a[u] = add2(M2a[u], __shfl_xor_sync(0xffffffffu, M2a[u], 16));
        kd2[u] = add2(kd2[u], __shfl_xor_sync(0xffffffffu, kd2[u], 16));
    }

    const int lane = tid & 31;
    const int w    = tid >> 5;
    if (lane < 16) {
        #pragma unroll
        for (int u = 0; u < 2; ++u) {
            const int j0 = lane + 32 * u, j1 = j0 + 16;
            float a, b;
            unpack2(qb2[u], a, b); red[0][w][j0] = a; red[0][w][j1] = b;
            unpack2(M0[u],  a, b); red[1][w][j0] = a; red[1][w][j1] = b;
            unpack2(M1[u],  a, b); red[2][w][j0] = a; red[2][w][j1] = b;
            unpack2(M2a[u], a, b); red[3][w][j0] = a; red[3][w][j1] = b;
            unpack2(kd2[u], a, b); red[4][w][j0] = a; red[4][w][j1] = b;
        }
    }
    __syncthreads();

    for (int vi = tid; vi < 320; vi += 256) {
        const int acc = vi >> 6, j = vi & 63;
        float s = 0.0f;
        #pragma unroll
        for (int ww = 0; ww < 8; ++ww) s += red[acc][ww][j];
        g_part[(size_t)blk * 320 + vi] = s;
    }

    // ---------------- fused finalize: last CTA per batch ----------------
    const int bb = blk >> 3;
    __syncthreads();                    // all g_part stores of this CTA done
    if (tid == 0) {
        __threadfence();                // publish g_part before counter bump
        s_old = atomicAdd(&g_cnt[bb], 1);
    }
    __syncthreads();
    if (s_old != 7) return;

    __threadfence();                    // acquire: see all 8 blocks' g_part

    const int j = tid;
    if (j < 64) {
        for (int h = 0; h < 2; ++h) {
            float qb = 0.0f, m0 = 0.0f, m1 = 0.0f, m2 = 0.0f, kd = 0.0f;
            const size_t base = (size_t)(bb * 8 + h * 4) * 320;
            #pragma unroll
            for (int s = 0; s < 4; ++s) {
                const float* p = g_part + base + (size_t)s * 320;
                qb += p[j];
                m0 += p[64 + j];
                m1 += p[128 + j];
                m2 += p[192 + j];
                kd += p[256 + j];
            }
            const float rkd = 1.0f / kd;
            float t[3];
            #pragma unroll
            for (int d = 0; d < 3; ++d) {
                const float kn = m0 * Wv[0 * 3 + d] + m1 * Wv[1 * 3 + d]
                               + m2 * Wv[2 * 3 + d] + bv[d] * kd;
                t[d] = qb * (kn * rkd);
            }
            #pragma unroll
            for (int o = 16; o >= 1; o >>= 1) {
                t[0] += __shfl_xor_sync(0xffffffffu, t[0], o);
                t[1] += __shfl_xor_sync(0xffffffffu, t[1], o);
                t[2] += __shfl_xor_sync(0xffffffffu, t[2], o);
            }
            const int ww = j >> 5;
            if ((j & 31) == 0) { fsh[ww][0] = t[0]; fsh[ww][1] = t[1]; fsh[ww][2] = t[2]; }
            __syncwarp(0xffffffffu);
            if (h == 0) {
                __syncthreads();
                if (j == 0)
                    for (int d = 0; d < 3; ++d)
                        ohalf[0][d] = (fsh[0][d] + fsh[1][d]) * (1.0f / 2048.0f);
                __syncthreads();
            }
        }
    } else {
        __syncthreads();
        __syncthreads();
    }
    __syncthreads();
    if (j == 0) {
        const float oh1_0 = (fsh[0][0] + fsh[1][0]) * (1.0f / 2048.0f);
        const float oh1_1 = (fsh[0][1] + fsh[1][1]) * (1.0f / 2048.0f);
        const float oh1_2 = (fsh[0][2] + fsh[1][2]) * (1.0f / 2048.0f);
        const float a0 = 0.5f * (ohalf[0][0] + oh1_0);
        const float a1 = 0.5f * (ohalf[0][1] + oh1_1);
        const float a2 = 0.5f * (ohalf[0][2] + oh1_2);
        const float inv = rsqrtf(a0 * a0 + a1 * a1 + a2 * a2);
        out[bb * 3 + 0] = a0 * inv;
        out[bb * 3 + 1] = a1 * inv;
        out[bb * 3 + 2] = a2 * inv;
        g_cnt[bb] = 0;                  // reset for next graph replay
    }
}

// ---------------------------------------------------------------------------
extern "C" void kernel_launch(void* const* d_in, const int* in_sizes, int n_in,
                              void* d_out, int out_size)
{
    const float* xin = (const float*)d_in[0];
    const float* Wq  = (const float*)d_in[1];
    const float* bq  = (const float*)d_in[2];
    const float* Wk  = (const float*)d_in[3];
    const float* bk  = (const float*)d_in[4];
    const float* Wv  = (const float*)d_in[5];
    const float* bv  = (const float*)d_in[6];
    float* out = (float*)d_out;

    ea_fused_kernel<<<2048, 256>>>(xin, Wq, bq, Wk, bk, Wv, bv, out);
}

// round 8
// speedup vs baseline: 1.1998x; 1.0087x over previous
#include <cuda_runtime.h>
#include <cstdint>

// ---------------------------------------------------------------------------
// EfficientAttention_Mapping: B=256, 2N=4096 (two halves of N=2048), D=3, DK=64
//
// Exact reformulation accumulated per (b,half):
//   qbar[j] = sum_n exp(lq[n,j]) / sum_j' exp(lq[n,j'])
//   kden[j] = sum_n exp(lk[n,j])
//   M[j][e] = sum_n exp(lk[n,j]) * x[n,e]     (e = 0..2)
// then
//   knum[j][d] = sum_e M[j][e]*Wv[e,d] + bv[d]*kden[j]
//   out_half[d] = (1/N) * sum_j qbar[j] * knum[j][d] / kden[j]
//
// Round 6: process TWO rows per loop iteration; both rows' softmax sums ride
// one packed 64-bit shfl butterfly (halves the per-row shfl chain exposure)
// and the two rows' logit/ex2 chains interleave for ILP.
// ---------------------------------------------------------------------------

typedef unsigned long long ull;

__device__ __forceinline__ ull pack2(float lo, float hi) {
    ull r; asm("mov.b64 %0, {%1, %2};" : "=l"(r) : "f"(lo), "f"(hi)); return r;
}
__device__ __forceinline__ void unpack2(ull v, float& lo, float& hi) {
    asm("mov.b64 {%0, %1}, %2;" : "=f"(lo), "=f"(hi) : "l"(v));
}
__device__ __forceinline__ ull fma2(ull a, ull b, ull c) {
    ull d; asm("fma.rn.f32x2 %0, %1, %2, %3;" : "=l"(d) : "l"(a), "l"(b), "l"(c)); return d;
}
__device__ __forceinline__ ull add2(ull a, ull b) {
    ull d; asm("add.rn.f32x2 %0, %1, %2;" : "=l"(d) : "l"(a), "l"(b)); return d;
}
__device__ __forceinline__ float ex2f(float x) {
    float y; asm("ex2.approx.ftz.f32 %0, %1;" : "=f"(y) : "f"(x)); return y;
}
__device__ __forceinline__ float rcpf(float x) {
    float y; asm("rcp.approx.ftz.f32 %0, %1;" : "=f"(y) : "f"(x)); return y;
}

#define LOG2E_F 1.4426950408889634f

// Scratch: 2048 row-blocks x 320 partials (qbar[64], M0[64], M1[64], M2[64], kden[64])
__device__ float g_part[2048 * 320];
__device__ int   g_cnt[256];   // zero-init; reset by finalizer each replay

__global__ __launch_bounds__(256, 3)
void ea_fused_kernel(const float* __restrict__ xin,
                     const float* __restrict__ Wq, const float* __restrict__ bq,
                     const float* __restrict__ Wk, const float* __restrict__ bk,
                     const float* __restrict__ Wv, const float* __restrict__ bv,
                     float* __restrict__ out)
{
    __shared__ ull         xs2[512 * 3];       // 12 KB: x chunk, value duplicated per pair
    __shared__ ulonglong2  wsu[4][2][16];      // 2 KB: weight pairs, pre-scaled by log2e
    __shared__ float       red[5][8][64];      // 10 KB: end-of-CTA reduction
    __shared__ int         s_old;
    __shared__ float       fsh[2][3];
    __shared__ float       ohalf[2][3];

    const int tid = threadIdx.x;
    const int blk = blockIdx.x;                // 0..2047; batch = blk>>3

    // --- stage x chunk as duplicated pairs (1536 scalars, coalesced) ---
    {
        const float* src = xin + (size_t)blk * 1536;
        #pragma unroll
        for (int i = tid; i < 1536; i += 256) {
            const float v = src[i];
            xs2[i] = pack2(v, v);
        }
    }

    // --- stage weights: wsu[sp][u][c]: pair (j0=c+32u, j1=j0+16)
    {
        float4* wf = reinterpret_cast<float4*>(&wsu[0][0][0]);
        for (int i = tid; i < 128; i += 256) {
            int c  = i & 15;
            int u  = (i >> 4) & 1;
            int sp = i >> 5;
            int j0 = c + 32 * u, j1 = j0 + 16;
            float a, b, cc, d;
            if (sp == 0)      { a = Wq[j0];       b = Wq[j1];       cc = Wq[64 + j0];  d = Wq[64 + j1]; }
            else if (sp == 1) { a = Wq[128 + j0]; b = Wq[128 + j1]; cc = bq[j0];       d = bq[j1]; }
            else if (sp == 2) { a = Wk[j0];       b = Wk[j1];       cc = Wk[64 + j0];  d = Wk[64 + j1]; }
            else              { a = Wk[128 + j0]; b = Wk[128 + j1]; cc = bk[j0];       d = bk[j1]; }
            wf[i] = make_float4(a * LOG2E_F, b * LOG2E_F, cc * LOG2E_F, d * LOG2E_F);
        }
    }
    __syncthreads();

    const int c = tid & 15;       // j-slice index within group (0..15)
    const int g = tid >> 4;       // group = row lane (16 groups)

    // hoist loop-invariant weights: 8 ulonglong2 = 32 regs
    const ulonglong2 wq01_0 = wsu[0][0][c], wq2b_0 = wsu[1][0][c];
    const ulonglong2 wk01_0 = wsu[2][0][c], wk2b_0 = wsu[3][0][c];
    const ulonglong2 wq01_1 = wsu[0][1][c], wq2b_1 = wsu[1][1][c];
    const ulonglong2 wk01_1 = wsu[2][1][c], wk2b_1 = wsu[3][1][c];

    const ull Z = pack2(0.0f, 0.0f);
    ull qb2[2], M0[2], M1[2], M2a[2], kd2[2];
    #pragma unroll
    for (int u = 0; u < 2; ++u) { qb2[u] = Z; M0[u] = Z; M1[u] = Z; M2a[u] = Z; kd2[u] = Z; }

    #pragma unroll 1
    for (int it = 0; it < 16; ++it) {
        const int rA = g + (it << 5);
        const int rB = rA + 16;
        const ull XA0 = xs2[rA * 3 + 0], XA1 = xs2[rA * 3 + 1], XA2 = xs2[rA * 3 + 2];
        const ull XB0 = xs2[rB * 3 + 0], XB1 = xs2[rB * 3 + 1], XB2 = xs2[rB * 3 + 2];

        // ---- row A ----
        ull lq0 = fma2(XA0, wq01_0.x, fma2(XA1, wq01_0.y, fma2(XA2, wq2b_0.x, wq2b_0.y)));
        ull lq1 = fma2(XA0, wq01_1.x, fma2(XA1, wq01_1.y, fma2(XA2, wq2b_1.x, wq2b_1.y)));
        ull lk0 = fma2(XA0, wk01_0.x, fma2(XA1, wk01_0.y, fma2(XA2, wk2b_0.x, wk2b_0.y)));
        ull lk1 = fma2(XA0, wk01_1.x, fma2(XA1, wk01_1.y, fma2(XA2, wk2b_1.x, wk2b_1.y)));

        float a, b;
        unpack2(lq0, a, b); const ull eq0A = pack2(ex2f(a), ex2f(b));
        unpack2(lq1, a, b); const ull eq1A = pack2(ex2f(a), ex2f(b));
        unpack2(lk0, a, b); ull ek = pack2(ex2f(a), ex2f(b));
        kd2[0] = add2(kd2[0], ek);
        M0[0]  = fma2(ek, XA0, M0[0]);
        M1[0]  = fma2(ek, XA1, M1[0]);
        M2a[0] = fma2(ek, XA2, M2a[0]);
        unpack2(lk1, a, b); ek = pack2(ex2f(a), ex2f(b));
        kd2[1] = add2(kd2[1], ek);
        M0[1]  = fma2(ek, XA0, M0[1]);
        M1[1]  = fma2(ek, XA1, M1[1]);
        M2a[1] = fma2(ek, XA2, M2a[1]);

        // ---- row B ----
        lq0 = fma2(XB0, wq01_0.x, fma2(XB1, wq01_0.y, fma2(XB2, wq2b_0.x, wq2b_0.y)));
        lq1 = fma2(XB0, wq01_1.x, fma2(XB1, wq01_1.y, fma2(XB2, wq2b_1.x, wq2b_1.y)));
        lk0 = fma2(XB0, wk01_0.x, fma2(XB1, wk01_0.y, fma2(XB2, wk2b_0.x, wk2b_0.y)));
        lk1 = fma2(XB0, wk01_1.x, fma2(XB1, wk01_1.y, fma2(XB2, wk2b_1.x, wk2b_1.y)));

        unpack2(lq0, a, b); const ull eq0B = pack2(ex2f(a), ex2f(b));
        unpack2(lq1, a, b); const ull eq1B = pack2(ex2f(a), ex2f(b));
        unpack2(lk0, a, b); ek = pack2(ex2f(a), ex2f(b));
        kd2[0] = add2(kd2[0], ek);
        M0[0]  = fma2(ek, XB0, M0[0]);
        M1[0]  = fma2(ek, XB1, M1[0]);
        M2a[0] = fma2(ek, XB2, M2a[0]);
        unpack2(lk1, a, b); ek = pack2(ex2f(a), ex2f(b));
        kd2[1] = add2(kd2[1], ek);
        M0[1]  = fma2(ek, XB0, M0[1]);
        M1[1]  = fma2(ek, XB1, M1[1]);
        M2a[1] = fma2(ek, XB2, M2a[1]);

        // ---- packed dual-row softmax-denominator butterfly ----
        ull tA = add2(eq0A, eq1A);
        ull tB = add2(eq0B, eq1B);
        float al, ah, bl, bh;
        unpack2(tA, al, ah);
        unpack2(tB, bl, bh);
        ull s2 = pack2(al + ah, bl + bh);      // (sumA, sumB) in one 64-bit value
        s2 = add2(s2, __shfl_xor_sync(0xffffffffu, s2, 1));
        s2 = add2(s2, __shfl_xor_sync(0xffffffffu, s2, 2));
        s2 = add2(s2, __shfl_xor_sync(0xffffffffu, s2, 4));
        s2 = add2(s2, __shfl_xor_sync(0xffffffffu, s2, 8));
        float sA, sB;
        unpack2(s2, sA, sB);
        const float rAinv = rcpf(sA);
        const float rBinv = rcpf(sB);
        const ull RA = pack2(rAinv, rAinv);
        const ull RB = pack2(rBinv, rBinv);

        qb2[0] = fma2(eq0A, RA, qb2[0]);
        qb2[1] = fma2(eq1A, RA, qb2[1]);
        qb2[0] = fma2(eq0B, RB, qb2[0]);
        qb2[1] = fma2(eq1B, RB, qb2[1]);
    }

    // --- combine the 2 groups within each warp (lanes differ in bit 4) ---
    #pragma unroll
    for (int u = 0; u < 2; ++u) {
        qb2[u] = add2(qb2[u], __shfl_xor_sync(0xffffffffu, qb2[u], 16));
        M0[u]  = add2(M0[u],  __shfl_xor_sync(0xffffffffu, M0[u],  16));
        M1[u]  = add2(M1[u],  __shfl_xor_sync(0xffffffffu, M1[u],  16));
        M2a[u] = add2(M2a[u], __shfl_xor_sync(0xffffffffu, M2a[u], 16));
        kd2[u] = add2(kd2[u], __shfl_xor_sync(0xffffffffu, kd2[u], 16));
    }

    const int lane = tid & 31;
    const int w    = tid >> 5;
    if (lane < 16) {
        #pragma unroll
        for (int u = 0; u < 2; ++u) {
            const int j0 = lane + 32 * u, j1 = j0 + 16;
            float a, b;
            unpack2(qb2[u], a, b); red[0][w][j0] = a; red[0][w][j1] = b;
            unpack2(M0[u],  a, b); red[1][w][j0] = a; red[1][w][j1] = b;
            unpack2(M1[u],  a, b); red[2][w][j0] = a; red[2][w][j1] = b;
            unpack2(M2a[u], a, b); red[3][w][j0] = a; red[3][w][j1] = b;
            unpack2(kd2[u], a, b); red[4][w][j0] = a; red[4][w][j1] = b;
        }
    }
    __syncthreads();

    for (int vi = tid; vi < 320; vi += 256) {
        const int acc = vi >> 6, j = vi & 63;
        float s = 0.0f;
        #pragma unroll
        for (int ww = 0; ww < 8; ++ww) s += red[acc][ww][j];
        g_part[(size_t)blk * 320 + vi] = s;
    }

    // ---------------- fused finalize: last CTA per batch ----------------
    const int bb = blk >> 3;
    __syncthreads();                    // all g_part stores of this CTA done
    if (tid == 0) {
        __threadfence();                // publish g_part before counter bump
        s_old = atomicAdd(&g_cnt[bb], 1);
    }
    __syncthreads();
    if (s_old != 7) return;

    __threadfence();                    // acquire: see all 8 blocks' g_part

    const int j = tid;
    if (j < 64) {
        for (int h = 0; h < 2; ++h) {
            float qb = 0.0f, m0 = 0.0f, m1 = 0.0f, m2 = 0.0f, kd = 0.0f;
            const size_t base = (size_t)(bb * 8 + h * 4) * 320;
            #pragma unroll
            for (int s = 0; s < 4; ++s) {
                const float* p = g_part + base + (size_t)s * 320;
                qb += p[j];
                m0 += p[64 + j];
                m1 += p[128 + j];
                m2 += p[192 + j];
                kd += p[256 + j];
            }
            const float rkd = 1.0f / kd;
            float t[3];
            #pragma unroll
            for (int d = 0; d < 3; ++d) {
                const float kn = m0 * Wv[0 * 3 + d] + m1 * Wv[1 * 3 + d]
                               + m2 * Wv[2 * 3 + d] + bv[d] * kd;
                t[d] = qb * (kn * rkd);
            }
            #pragma unroll
            for (int o = 16; o >= 1; o >>= 1) {
                t[0] += __shfl_xor_sync(0xffffffffu, t[0], o);
                t[1] += __shfl_xor_sync(0xffffffffu, t[1], o);
                t[2] += __shfl_xor_sync(0xffffffffu, t[2], o);
            }
            const int ww = j >> 5;
            if ((j & 31) == 0) { fsh[ww][0] = t[0]; fsh[ww][1] = t[1]; fsh[ww][2] = t[2]; }
            __syncwarp(0xffffffffu);
            if (h == 0) {
                __syncthreads();
                if (j == 0)
                    for (int d = 0; d < 3; ++d)
                        ohalf[0][d] = (fsh[0][d] + fsh[1][d]) * (1.0f / 2048.0f);
                __syncthreads();
            }
        }
    } else {
        __syncthreads();
        __syncthreads();
    }
    __syncthreads();
    if (j == 0) {
        const float oh1_0 = (fsh[0][0] + fsh[1][0]) * (1.0f / 2048.0f);
        const float oh1_1 = (fsh[0][1] + fsh[1][1]) * (1.0f / 2048.0f);
        const float oh1_2 = (fsh[0][2] + fsh[1][2]) * (1.0f / 2048.0f);
        const float a0 = 0.5f * (ohalf[0][0] + oh1_0);
        const float a1 = 0.5f * (ohalf[0][1] + oh1_1);
        const float a2 = 0.5f * (ohalf[0][2] + oh1_2);
        const float inv = rsqrtf(a0 * a0 + a1 * a1 + a2 * a2);
        out[bb * 3 + 0] = a0 * inv;
        out[bb * 3 + 1] = a1 * inv;
        out[bb * 3 + 2] = a2 * inv;
        g_cnt[bb] = 0;                  // reset for next graph replay
    }
}

// ---------------------------------------------------------------------------
extern "C" void kernel_launch(void* const* d_in, const int* in_sizes, int n_in,
                              void* d_out, int out_size)
{
    const float* xin = (const float*)d_in[0];
    const float* Wq  = (const float*)d_in[1];
    const float* bq  = (const float*)d_in[2];
    const float* Wk  = (const float*)d_in[3];
    const float* bk  = (const float*)d_in[4];
    const float* Wv  = (const float*)d_in[5];
    const float* bv  = (const float*)d_in[6];
    float* out = (float*)d_out;

    ea_fused_kernel<<<2048, 256>>>(xin, Wq, bq, Wk, bk, Wv, bv, out);
}